// round 6
// baseline (speedup 1.0000x reference)
#include <cuda_runtime.h>

// Problem constants
#define B_ 4
#define N_ 1024
#define H_ 64
#define D_ 64
#define FE_ 16

// Scratch (allocation-free: __device__ globals)
__device__ float g_z[B_ * N_ * D_];       // 1 MB
__device__ float g_si[B_ * N_];
__device__ float g_sj[B_ * N_];
__device__ float g_rowsum[B_ * N_];

// Side stream + events, created at static-init time (before the harness's
// memory checkpoints), so nothing is allocated inside kernel_launch.
static cudaStream_t g_s2;
static cudaEvent_t g_ev_fork, g_ev_join;
namespace {
struct StreamInit {
    StreamInit() {
        cudaStreamCreateWithFlags(&g_s2, cudaStreamNonBlocking);
        cudaEventCreateWithFlags(&g_ev_fork, cudaEventDisableTiming);
        cudaEventCreateWithFlags(&g_ev_join, cudaEventDisableTiming);
    }
};
static StreamInit g_stream_init;
}

// ---------------------------------------------------------------------------
// k_sisj: si/sj WITHOUT z.  sj[r] = h0[r,:]·u1, si[r] = h0[r,:]·u2, where
// u1 = w_fc^T a1, u2 = w_fc^T a2 (64-vectors, computed redundantly per block
// -- 8K FMAs, trivial). 16 blocks x 256 threads; thread = one row.
// ---------------------------------------------------------------------------
__global__ void __launch_bounds__(256) k_sisj(const float* __restrict__ h0,
                                              const float* __restrict__ w_fc,
                                              const float* __restrict__ w_attn) {
    __shared__ __align__(16) float u1[H_];
    __shared__ __align__(16) float u2[H_];

    const int t = threadIdx.x;
    if (t < 128) {
        const int h = t & 63;
        const float* col = w_fc + h;                 // w_fc[d*64 + h]
        const float* a = w_attn + (t >> 6) * D_;     // a1 (t<64) or a2
        float acc = 0.f;
#pragma unroll
        for (int d = 0; d < D_; ++d)
            acc = fmaf(col[d * H_], __ldg(&a[d]), acc);
        if (t < 64) u1[h] = acc; else u2[h] = acc;
    }
    __syncthreads();

    const int row = blockIdx.x * 256 + t;            // < 4096
    const float4* hv = reinterpret_cast<const float4*>(h0) + row * (H_ / 4);
    const float4* u1v = reinterpret_cast<const float4*>(u1);
    const float4* u2v = reinterpret_cast<const float4*>(u2);
    float s1 = 0.f, s2 = 0.f;
#pragma unroll
    for (int q = 0; q < H_ / 4; ++q) {
        const float4 v = __ldg(&hv[q]);
        const float4 w1 = u1v[q];                    // smem broadcast
        const float4 w2 = u2v[q];
        s1 = fmaf(v.x, w1.x, s1); s2 = fmaf(v.x, w2.x, s2);
        s1 = fmaf(v.y, w1.y, s1); s2 = fmaf(v.y, w2.y, s2);
        s1 = fmaf(v.z, w1.z, s1); s2 = fmaf(v.z, w2.z, s2);
        s1 = fmaf(v.w, w1.w, s1); s2 = fmaf(v.w, w2.w, s2);
    }
    g_sj[row] = s1;
    g_si[row] = s2;
}

// ---------------------------------------------------------------------------
// k_z: pure z GEMM (si/sj epilogue removed). Single wave: 128 blocks x 512
// threads, 32 rows/block, 4 rows/thread. Runs on the side stream, overlapped
// with k_row (its output is only needed by k_finish).
// ---------------------------------------------------------------------------
#define RPB 32
#define WPITCH 65
__global__ void __launch_bounds__(512) k_z(const float* __restrict__ h0,
                                           const float* __restrict__ w_fc) {
    __shared__ float wT[H_ * WPITCH];               // wT[h*65+d] = w_fc[d*64+h]
    __shared__ __align__(16) float h0s[RPB * H_];

    const int t = threadIdx.x;
    const int row0 = blockIdx.x * RPB;

#pragma unroll
    for (int idx = t; idx < H_ * D_; idx += 512) {
        const int d = idx >> 6, h = idx & 63;
        wT[h * WPITCH + d] = w_fc[idx];
    }
#pragma unroll
    for (int idx = t; idx < RPB * H_; idx += 512)
        h0s[idx] = h0[row0 * H_ + idx];
    __syncthreads();

    const int d  = t & 63;
    const int rg = t >> 6;                 // 0..7, 4 rows each
    const float4* h0v = reinterpret_cast<const float4*>(h0s);
    const int rbase = rg * 4;

    float acc0 = 0.f, acc1 = 0.f, acc2 = 0.f, acc3 = 0.f;
#pragma unroll
    for (int h4 = 0; h4 < H_ / 4; ++h4) {
        const float4 a0 = h0v[(rbase + 0) * (H_ / 4) + h4];
        const float4 a1 = h0v[(rbase + 1) * (H_ / 4) + h4];
        const float4 a2 = h0v[(rbase + 2) * (H_ / 4) + h4];
        const float4 a3 = h0v[(rbase + 3) * (H_ / 4) + h4];
        const float w0 = wT[(h4 * 4 + 0) * WPITCH + d];
        const float w1 = wT[(h4 * 4 + 1) * WPITCH + d];
        const float w2 = wT[(h4 * 4 + 2) * WPITCH + d];
        const float w3 = wT[(h4 * 4 + 3) * WPITCH + d];
        acc0 = fmaf(a0.x, w0, acc0); acc1 = fmaf(a1.x, w0, acc1);
        acc2 = fmaf(a2.x, w0, acc2); acc3 = fmaf(a3.x, w0, acc3);
        acc0 = fmaf(a0.y, w1, acc0); acc1 = fmaf(a1.y, w1, acc1);
        acc2 = fmaf(a2.y, w1, acc2); acc3 = fmaf(a3.y, w1, acc3);
        acc0 = fmaf(a0.z, w2, acc0); acc1 = fmaf(a1.z, w2, acc1);
        acc2 = fmaf(a2.z, w2, acc2); acc3 = fmaf(a3.z, w2, acc3);
        acc0 = fmaf(a0.w, w3, acc0); acc1 = fmaf(a1.w, w3, acc1);
        acc2 = fmaf(a2.w, w3, acc2); acc3 = fmaf(a3.w, w3, acc3);
    }

    const int r = row0 + rbase;
    g_z[(r + 0) * D_ + d] = acc0;
    g_z[(r + 1) * D_ + d] = acc1;
    g_z[(r + 2) * D_ + d] = acc2;
    g_z[(r + 3) * D_ + d] = acc3;
}

// ---------------------------------------------------------------------------
// k_row: one block per (b,i) row, 256 threads, streams 64KB of e with
// lane-contiguous float4 loads. 4-lane group completes the 16-feature dot
// via two shfl_xor; exp computed 4x redundantly, rowsum scaled by 0.25.
// rowsum[b,i] = sum_j exp(leaky_relu(si[b,i] + sj[b,j] + <e[b,i,j,:], a3>))
// ---------------------------------------------------------------------------
__global__ void __launch_bounds__(256) k_row(const float* __restrict__ e,
                                             const float* __restrict__ w_attn) {
    __shared__ float sjs[N_];
    __shared__ float red[8];

    const int row = blockIdx.x;      // b*N + i
    const int b = row >> 10;
    const int t = threadIdx.x;
    const int lane = t & 31;
    const int w = t >> 5;

#pragma unroll
    for (int j = t; j < N_; j += 256) sjs[j] = g_sj[b * N_ + j];
    __syncthreads();

    const int fg = (lane & 3) * 4;
    const float af0 = __ldg(&w_attn[2 * D_ + fg + 0]);
    const float af1 = __ldg(&w_attn[2 * D_ + fg + 1]);
    const float af2 = __ldg(&w_attn[2 * D_ + fg + 2]);
    const float af3 = __ldg(&w_attn[2 * D_ + fg + 3]);

    const float si = g_si[row];
    const float4* e4 = reinterpret_cast<const float4*>(e) + (size_t)row * (N_ * 4);

    float acc = 0.f;
#pragma unroll 8
    for (int idx4 = t; idx4 < N_ * 4; idx4 += 256) {
        const float4 v = __ldcs(&e4[idx4]);
        float p = v.x * af0;
        p = fmaf(v.y, af1, p);
        p = fmaf(v.z, af2, p);
        p = fmaf(v.w, af3, p);
        p += __shfl_xor_sync(0xffffffffu, p, 1);
        p += __shfl_xor_sync(0xffffffffu, p, 2);
        const int j = idx4 >> 2;
        float s = si + sjs[j] + p;
        s = (s >= 0.f) ? s : 0.01f * s;              // leaky_relu
        acc += __expf(s);
    }

#pragma unroll
    for (int o = 16; o; o >>= 1) acc += __shfl_down_sync(0xffffffffu, acc, o);
    if (lane == 0) red[w] = acc;
    __syncthreads();
    if (t == 0) {
        float s = 0.f;
#pragma unroll
        for (int k = 0; k < 8; ++k) s += red[k];
        g_rowsum[row] = 0.25f * s;
    }
}

// ---------------------------------------------------------------------------
// k_finish: one 64-thread block per row. Deterministic redundant reduction of
// the batch's 1024 rowsums (L2-resident), then scale the z row.
// ---------------------------------------------------------------------------
__global__ void __launch_bounds__(64) k_finish(float* __restrict__ out) {
    __shared__ float red[2];
    const int row = blockIdx.x;
    const int b = row >> 10;
    const int t = threadIdx.x;

    const float4* rs4 = reinterpret_cast<const float4*>(g_rowsum) + b * 256;
    float acc = 0.f;
#pragma unroll
    for (int k = t; k < 256; k += 64) {
        const float4 v = rs4[k];
        acc += (v.x + v.y) + (v.z + v.w);
    }
#pragma unroll
    for (int o = 16; o; o >>= 1) acc += __shfl_down_sync(0xffffffffu, acc, o);
    if ((t & 31) == 0) red[t >> 5] = acc;
    __syncthreads();
    const float total = red[0] + red[1];
    const float scale = g_rowsum[row] * (1.0f / total);
    out[row * D_ + t] = scale * g_z[row * D_ + t];
}

// ---------------------------------------------------------------------------
extern "C" void kernel_launch(void* const* d_in, const int* in_sizes, int n_in,
                              void* d_out, int out_size) {
    const float* h0     = (const float*)d_in[0];   // (B,N,H)
    const float* e      = (const float*)d_in[1];   // (B,N,N,FE)
    const float* w_fc   = (const float*)d_in[2];   // (D,H)
    const float* w_attn = (const float*)d_in[3];   // (2D+FE,)
    float* out = (float*)d_out;                    // (B,N,D)

    // Fork: z GEMM runs on the side stream, overlapped with k_sisj + k_row.
    cudaEventRecord(g_ev_fork, 0);
    cudaStreamWaitEvent(g_s2, g_ev_fork, 0);
    k_z<<<(B_ * N_) / RPB, 512, 0, g_s2>>>(h0, w_fc);

    k_sisj<<<(B_ * N_) / 256, 256>>>(h0, w_fc, w_attn);
    k_row<<<B_ * N_, 256>>>(e, w_attn);

    // Join: k_finish needs both g_rowsum (main stream) and g_z (side stream).
    cudaEventRecord(g_ev_join, g_s2);
    cudaStreamWaitEvent(0, g_ev_join, 0);
    k_finish<<<B_ * N_, 64>>>(out);
}

// round 7
// speedup vs baseline: 1.1151x; 1.1151x over previous
#include <cuda_runtime.h>

// Problem constants
#define B_ 4
#define N_ 1024
#define H_ 64
#define D_ 64
#define FE_ 16

// Scratch (allocation-free: __device__ globals)
__device__ float g_si[B_ * N_];
__device__ float g_sj[B_ * N_];
__device__ float g_rowsum[B_ * N_];

// ---------------------------------------------------------------------------
// k_sisj: si/sj WITHOUT z.  sj[r] = h0[r,:]·u1, si[r] = h0[r,:]·u2, where
// u1 = w_fc^T a1, u2 = w_fc^T a2 (computed redundantly per block — 8K FMAs).
// 32 blocks x 128 threads; one row per thread.
// ---------------------------------------------------------------------------
__global__ void __launch_bounds__(128) k_sisj(const float* __restrict__ h0,
                                              const float* __restrict__ w_fc,
                                              const float* __restrict__ w_attn) {
    __shared__ __align__(16) float u1[H_];
    __shared__ __align__(16) float u2[H_];

    const int t = threadIdx.x;
    {
        const int h = t & 63;
        const float* col = w_fc + h;                 // w_fc[d*64 + h]
        const float* a = w_attn + (t >> 6) * D_;     // a1 (t<64) or a2
        float acc = 0.f;
#pragma unroll
        for (int d = 0; d < D_; ++d)
            acc = fmaf(col[d * H_], __ldg(&a[d]), acc);
        if (t < 64) u1[h] = acc; else u2[h] = acc;
    }
    __syncthreads();

    const int row = blockIdx.x * 128 + t;            // < 4096
    const float4* hv = reinterpret_cast<const float4*>(h0) + row * (H_ / 4);
    const float4* u1v = reinterpret_cast<const float4*>(u1);
    const float4* u2v = reinterpret_cast<const float4*>(u2);
    float s1 = 0.f, s2 = 0.f;
#pragma unroll
    for (int q = 0; q < H_ / 4; ++q) {
        const float4 v = __ldg(&hv[q]);
        const float4 w1 = u1v[q];
        const float4 w2 = u2v[q];
        s1 = fmaf(v.x, w1.x, s1); s2 = fmaf(v.x, w2.x, s2);
        s1 = fmaf(v.y, w1.y, s1); s2 = fmaf(v.y, w2.y, s2);
        s1 = fmaf(v.z, w1.z, s1); s2 = fmaf(v.z, w2.z, s2);
        s1 = fmaf(v.w, w1.w, s1); s2 = fmaf(v.w, w2.w, s2);
    }
    g_sj[row] = s1;
    g_si[row] = s2;
}

// ---------------------------------------------------------------------------
// k_row: one block per (b,i) row, 256 threads, streams 64KB of e with
// lane-contiguous float4 loads. 4-lane group completes the 16-feature dot
// via two shfl_xor; exp computed 4x redundantly, rowsum scaled by 0.25.
// rowsum[b,i] = sum_j exp(leaky_relu(si[b,i] + sj[b,j] + <e[b,i,j,:], a3>))
// (measured at the 256MB DRAM floor, ~37us)
// ---------------------------------------------------------------------------
__global__ void __launch_bounds__(256) k_row(const float* __restrict__ e,
                                             const float* __restrict__ w_attn) {
    __shared__ float sjs[N_];
    __shared__ float red[8];

    const int row = blockIdx.x;      // b*N + i
    const int b = row >> 10;
    const int t = threadIdx.x;
    const int lane = t & 31;
    const int w = t >> 5;

#pragma unroll
    for (int j = t; j < N_; j += 256) sjs[j] = g_sj[b * N_ + j];
    __syncthreads();

    const int fg = (lane & 3) * 4;
    const float af0 = __ldg(&w_attn[2 * D_ + fg + 0]);
    const float af1 = __ldg(&w_attn[2 * D_ + fg + 1]);
    const float af2 = __ldg(&w_attn[2 * D_ + fg + 2]);
    const float af3 = __ldg(&w_attn[2 * D_ + fg + 3]);

    const float si = g_si[row];
    const float4* e4 = reinterpret_cast<const float4*>(e) + (size_t)row * (N_ * 4);

    float acc = 0.f;
#pragma unroll 8
    for (int idx4 = t; idx4 < N_ * 4; idx4 += 256) {
        const float4 v = __ldcs(&e4[idx4]);
        float p = v.x * af0;
        p = fmaf(v.y, af1, p);
        p = fmaf(v.z, af2, p);
        p = fmaf(v.w, af3, p);
        p += __shfl_xor_sync(0xffffffffu, p, 1);
        p += __shfl_xor_sync(0xffffffffu, p, 2);
        const int j = idx4 >> 2;
        float s = si + sjs[j] + p;
        s = (s >= 0.f) ? s : 0.01f * s;              // leaky_relu
        acc += __expf(s);
    }

#pragma unroll
    for (int o = 16; o; o >>= 1) acc += __shfl_down_sync(0xffffffffu, acc, o);
    if (lane == 0) red[w] = acc;
    __syncthreads();
    if (t == 0) {
        float s = 0.f;
#pragma unroll
        for (int k = 0; k < 8; ++k) s += red[k];
        g_rowsum[row] = 0.25f * s;
    }
}

// ---------------------------------------------------------------------------
// k_zout: FUSED z-GEMM + softmax-scale epilogue. Single wave: 128 blocks x
// 512 threads, 32 rows/block, 4 rows/thread.
//   z[r,d] = sum_h h0[r,h]*w_fc[d,h]
//   out[r,d] = (rowsum[r] / total[b]) * z[r,d]
// total[b] reduced deterministically (and redundantly) per block from the
// batch's 1024 rowsums (4KB, L2-resident). g_z eliminated entirely.
// ---------------------------------------------------------------------------
#define RPB 32
#define WPITCH 65
__global__ void __launch_bounds__(512) k_zout(const float* __restrict__ h0,
                                              const float* __restrict__ w_fc,
                                              float* __restrict__ out) {
    __shared__ float wT[H_ * WPITCH];               // wT[h*65+d] = w_fc[d*64+h]
    __shared__ __align__(16) float h0s[RPB * H_];
    __shared__ float red[16];
    __shared__ float rs_rows[RPB];
    __shared__ float s_total;

    const int t = threadIdx.x;
    const int row0 = blockIdx.x * RPB;
    const int b = blockIdx.x >> 5;                   // 32 blocks per batch

    // stage w_fc transposed (store stride 65*4B: conflict-free)
#pragma unroll
    for (int idx = t; idx < H_ * D_; idx += 512) {
        const int d = idx >> 6, h = idx & 63;
        wT[h * WPITCH + d] = w_fc[idx];
    }
#pragma unroll
    for (int idx = t; idx < RPB * H_; idx += 512)
        h0s[idx] = h0[row0 * H_ + idx];

    // batch-total reduction (deterministic tree): each thread 2 rowsums
    {
        float a = g_rowsum[b * N_ + t] + g_rowsum[b * N_ + t + 512];
#pragma unroll
        for (int o = 16; o; o >>= 1) a += __shfl_down_sync(0xffffffffu, a, o);
        if ((t & 31) == 0) red[t >> 5] = a;
    }
    if (t < RPB) rs_rows[t] = g_rowsum[row0 + t];
    __syncthreads();

    if (t == 0) {
        float s = 0.f;
#pragma unroll
        for (int k = 0; k < 16; ++k) s += red[k];
        s_total = s;
    }

    const int d  = t & 63;
    const int rg = t >> 6;                 // 0..7, 4 rows each
    const float4* h0v = reinterpret_cast<const float4*>(h0s);
    const int rbase = rg * 4;

    float acc0 = 0.f, acc1 = 0.f, acc2 = 0.f, acc3 = 0.f;
#pragma unroll
    for (int h4 = 0; h4 < H_ / 4; ++h4) {
        const float4 a0 = h0v[(rbase + 0) * (H_ / 4) + h4];
        const float4 a1 = h0v[(rbase + 1) * (H_ / 4) + h4];
        const float4 a2 = h0v[(rbase + 2) * (H_ / 4) + h4];
        const float4 a3 = h0v[(rbase + 3) * (H_ / 4) + h4];
        const float w0 = wT[(h4 * 4 + 0) * WPITCH + d];
        const float w1 = wT[(h4 * 4 + 1) * WPITCH + d];
        const float w2 = wT[(h4 * 4 + 2) * WPITCH + d];
        const float w3 = wT[(h4 * 4 + 3) * WPITCH + d];
        acc0 = fmaf(a0.x, w0, acc0); acc1 = fmaf(a1.x, w0, acc1);
        acc2 = fmaf(a2.x, w0, acc2); acc3 = fmaf(a3.x, w0, acc3);
        acc0 = fmaf(a0.y, w1, acc0); acc1 = fmaf(a1.y, w1, acc1);
        acc2 = fmaf(a2.y, w1, acc2); acc3 = fmaf(a3.y, w1, acc3);
        acc0 = fmaf(a0.z, w2, acc0); acc1 = fmaf(a1.z, w2, acc1);
        acc2 = fmaf(a2.z, w2, acc2); acc3 = fmaf(a3.z, w2, acc3);
        acc0 = fmaf(a0.w, w3, acc0); acc1 = fmaf(a1.w, w3, acc1);
        acc2 = fmaf(a2.w, w3, acc2); acc3 = fmaf(a3.w, w3, acc3);
    }
    __syncthreads();                       // s_total ready

    const float inv = 1.0f / s_total;
    const int r = row0 + rbase;
    out[(r + 0) * D_ + d] = rs_rows[rbase + 0] * inv * acc0;
    out[(r + 1) * D_ + d] = rs_rows[rbase + 1] * inv * acc1;
    out[(r + 2) * D_ + d] = rs_rows[rbase + 2] * inv * acc2;
    out[(r + 3) * D_ + d] = rs_rows[rbase + 3] * inv * acc3;
}

// ---------------------------------------------------------------------------
extern "C" void kernel_launch(void* const* d_in, const int* in_sizes, int n_in,
                              void* d_out, int out_size) {
    const float* h0     = (const float*)d_in[0];   // (B,N,H)
    const float* e      = (const float*)d_in[1];   // (B,N,N,FE)
    const float* w_fc   = (const float*)d_in[2];   // (D,H)
    const float* w_attn = (const float*)d_in[3];   // (2D+FE,)
    float* out = (float*)d_out;                    // (B,N,D)

    k_sisj<<<(B_ * N_) / 128, 128>>>(h0, w_fc, w_attn);
    k_row<<<B_ * N_, 256>>>(e, w_attn);
    k_zout<<<(B_ * N_) / RPB, 512>>>(h0, w_fc, out);
}

// round 8
// speedup vs baseline: 1.1158x; 1.0006x over previous
#include <cuda_runtime.h>

// Problem constants
#define B_ 4
#define N_ 1024
#define H_ 64
#define D_ 64
#define FE_ 16

// Scratch (allocation-free: __device__ globals)
__device__ float g_si[B_ * N_];
__device__ float g_sj[B_ * N_];
__device__ float g_rowsum[B_ * N_];

// ---------------------------------------------------------------------------
// k_sisj v2: sj[r] = h0[r,:]·u1, si[r] = h0[r,:]·u2  (u1 = w_fc^T a1, etc.)
// Latency-hiding restructure (R7 version was 8.2us, DRAM-latency bound):
//   1. prefetch h0 row into 16 float4 regs (independent LDGs, one DRAM round)
//   2. stage all of w_fc (16KB) into smem with coalesced float4 loads
//   3. compute u1/u2 from SMEM (conflict-free LDS; no strided global loads)
//   4. finish row dot from registers + smem-broadcast u
// 32 blocks x 128 threads, one row per thread.
// ---------------------------------------------------------------------------
__global__ void __launch_bounds__(128) k_sisj(const float* __restrict__ h0,
                                              const float* __restrict__ w_fc,
                                              const float* __restrict__ w_attn) {
    __shared__ __align__(16) float wfs[H_ * D_];    // 16 KB, same layout as w_fc
    __shared__ __align__(16) float u1[H_];
    __shared__ __align__(16) float u2[H_];

    const int t = threadIdx.x;
    const int row = blockIdx.x * 128 + t;           // < 4096

    // (1) prefetch h0 row — 16 independent LDG.128, coalesced in float4 units
    const float4* hv4 = reinterpret_cast<const float4*>(h0) + row * (H_ / 4);
    float4 hreg[16];
#pragma unroll
    for (int q = 0; q < 16; ++q) hreg[q] = __ldg(&hv4[q]);

    // (2) stage w_fc into smem, coalesced (1024 float4 total, 8 per thread)
    const float4* w4 = reinterpret_cast<const float4*>(w_fc);
    float4* ws4 = reinterpret_cast<float4*>(wfs);
#pragma unroll
    for (int k = 0; k < 8; ++k) ws4[k * 128 + t] = w4[k * 128 + t];
    __syncthreads();

    // (3) u[h] = sum_d wfs[d*64+h] * a[d]; lanes vary h -> conflict-free LDS,
    //     a[d] uniform per warp (L1-cached global).
    {
        const int h = t & 63;
        const float* a = w_attn + (t >> 6) * D_;    // a1 (t<64) or a2
        const float* col = wfs + h;
        float acc = 0.f;
#pragma unroll
        for (int d = 0; d < D_; ++d)
            acc = fmaf(col[d * H_], __ldg(&a[d]), acc);
        if (t < 64) u1[h] = acc; else u2[t - 64] = acc;
    }
    __syncthreads();

    // (4) row dots from registers + smem broadcasts
    const float4* u1v = reinterpret_cast<const float4*>(u1);
    const float4* u2v = reinterpret_cast<const float4*>(u2);
    float s1 = 0.f, s2 = 0.f;
#pragma unroll
    for (int q = 0; q < 16; ++q) {
        const float4 v = hreg[q];
        const float4 w1 = u1v[q];
        const float4 w2 = u2v[q];
        s1 = fmaf(v.x, w1.x, s1); s2 = fmaf(v.x, w2.x, s2);
        s1 = fmaf(v.y, w1.y, s1); s2 = fmaf(v.y, w2.y, s2);
        s1 = fmaf(v.z, w1.z, s1); s2 = fmaf(v.z, w2.z, s2);
        s1 = fmaf(v.w, w1.w, s1); s2 = fmaf(v.w, w2.w, s2);
    }
    g_sj[row] = s1;
    g_si[row] = s2;
}

// ---------------------------------------------------------------------------
// k_row: one block per (b,i) row, 256 threads, streams 64KB of e with
// lane-contiguous float4 loads. 4-lane group completes the 16-feature dot
// via two shfl_xor; exp computed 4x redundantly, rowsum scaled by 0.25.
// rowsum[b,i] = sum_j exp(leaky_relu(si[b,i] + sj[b,j] + <e[b,i,j,:], a3>))
// (measured at the 256MB DRAM floor, ~36-37us)
// ---------------------------------------------------------------------------
__global__ void __launch_bounds__(256) k_row(const float* __restrict__ e,
                                             const float* __restrict__ w_attn) {
    __shared__ float sjs[N_];
    __shared__ float red[8];

    const int row = blockIdx.x;      // b*N + i
    const int b = row >> 10;
    const int t = threadIdx.x;
    const int lane = t & 31;
    const int w = t >> 5;

#pragma unroll
    for (int j = t; j < N_; j += 256) sjs[j] = g_sj[b * N_ + j];
    __syncthreads();

    const int fg = (lane & 3) * 4;
    const float af0 = __ldg(&w_attn[2 * D_ + fg + 0]);
    const float af1 = __ldg(&w_attn[2 * D_ + fg + 1]);
    const float af2 = __ldg(&w_attn[2 * D_ + fg + 2]);
    const float af3 = __ldg(&w_attn[2 * D_ + fg + 3]);

    const float si = g_si[row];
    const float4* e4 = reinterpret_cast<const float4*>(e) + (size_t)row * (N_ * 4);

    float acc = 0.f;
#pragma unroll 8
    for (int idx4 = t; idx4 < N_ * 4; idx4 += 256) {
        const float4 v = __ldcs(&e4[idx4]);
        float p = v.x * af0;
        p = fmaf(v.y, af1, p);
        p = fmaf(v.z, af2, p);
        p = fmaf(v.w, af3, p);
        p += __shfl_xor_sync(0xffffffffu, p, 1);
        p += __shfl_xor_sync(0xffffffffu, p, 2);
        const int j = idx4 >> 2;
        float s = si + sjs[j] + p;
        s = (s >= 0.f) ? s : 0.01f * s;              // leaky_relu
        acc += __expf(s);
    }

#pragma unroll
    for (int o = 16; o; o >>= 1) acc += __shfl_down_sync(0xffffffffu, acc, o);
    if (lane == 0) red[w] = acc;
    __syncthreads();
    if (t == 0) {
        float s = 0.f;
#pragma unroll
        for (int k = 0; k < 8; ++k) s += red[k];
        g_rowsum[row] = 0.25f * s;
    }
}

// ---------------------------------------------------------------------------
// k_zout: FUSED z-GEMM + softmax-scale epilogue. Single wave: 128 blocks x
// 512 threads, 32 rows/block, 4 rows/thread.
//   out[r,d] = (rowsum[r] / total[b]) * sum_h h0[r,h]*w_fc[d,h]
// total[b] reduced deterministically (redundantly) per block from the
// batch's 1024 rowsums (4KB, L2-resident).
// ---------------------------------------------------------------------------
#define RPB 32
#define WPITCH 65
__global__ void __launch_bounds__(512) k_zout(const float* __restrict__ h0,
                                              const float* __restrict__ w_fc,
                                              float* __restrict__ out) {
    __shared__ float wT[H_ * WPITCH];               // wT[h*65+d] = w_fc[d*64+h]
    __shared__ __align__(16) float h0s[RPB * H_];
    __shared__ float red[16];
    __shared__ float rs_rows[RPB];
    __shared__ float s_total;

    const int t = threadIdx.x;
    const int row0 = blockIdx.x * RPB;
    const int b = blockIdx.x >> 5;                   // 32 blocks per batch

#pragma unroll
    for (int idx = t; idx < H_ * D_; idx += 512) {
        const int d = idx >> 6, h = idx & 63;
        wT[h * WPITCH + d] = w_fc[idx];
    }
#pragma unroll
    for (int idx = t; idx < RPB * H_; idx += 512)
        h0s[idx] = h0[row0 * H_ + idx];

    // batch-total reduction (deterministic tree): each thread 2 rowsums
    {
        float a = g_rowsum[b * N_ + t] + g_rowsum[b * N_ + t + 512];
#pragma unroll
        for (int o = 16; o; o >>= 1) a += __shfl_down_sync(0xffffffffu, a, o);
        if ((t & 31) == 0) red[t >> 5] = a;
    }
    if (t < RPB) rs_rows[t] = g_rowsum[row0 + t];
    __syncthreads();

    if (t == 0) {
        float s = 0.f;
#pragma unroll
        for (int k = 0; k < 16; ++k) s += red[k];
        s_total = s;
    }

    const int d  = t & 63;
    const int rg = t >> 6;                 // 0..7, 4 rows each
    const float4* h0v = reinterpret_cast<const float4*>(h0s);
    const int rbase = rg * 4;

    float acc0 = 0.f, acc1 = 0.f, acc2 = 0.f, acc3 = 0.f;
#pragma unroll
    for (int h4 = 0; h4 < H_ / 4; ++h4) {
        const float4 a0 = h0v[(rbase + 0) * (H_ / 4) + h4];
        const float4 a1 = h0v[(rbase + 1) * (H_ / 4) + h4];
        const float4 a2 = h0v[(rbase + 2) * (H_ / 4) + h4];
        const float4 a3 = h0v[(rbase + 3) * (H_ / 4) + h4];
        const float w0 = wT[(h4 * 4 + 0) * WPITCH + d];
        const float w1 = wT[(h4 * 4 + 1) * WPITCH + d];
        const float w2 = wT[(h4 * 4 + 2) * WPITCH + d];
        const float w3 = wT[(h4 * 4 + 3) * WPITCH + d];
        acc0 = fmaf(a0.x, w0, acc0); acc1 = fmaf(a1.x, w0, acc1);
        acc2 = fmaf(a2.x, w0, acc2); acc3 = fmaf(a3.x, w0, acc3);
        acc0 = fmaf(a0.y, w1, acc0); acc1 = fmaf(a1.y, w1, acc1);
        acc2 = fmaf(a2.y, w1, acc2); acc3 = fmaf(a3.y, w1, acc3);
        acc0 = fmaf(a0.z, w2, acc0); acc1 = fmaf(a1.z, w2, acc1);
        acc2 = fmaf(a2.z, w2, acc2); acc3 = fmaf(a3.z, w2, acc3);
        acc0 = fmaf(a0.w, w3, acc0); acc1 = fmaf(a1.w, w3, acc1);
        acc2 = fmaf(a2.w, w3, acc2); acc3 = fmaf(a3.w, w3, acc3);
    }
    __syncthreads();                       // s_total ready

    const float inv = 1.0f / s_total;
    const int r = row0 + rbase;
    out[(r + 0) * D_ + d] = rs_rows[rbase + 0] * inv * acc0;
    out[(r + 1) * D_ + d] = rs_rows[rbase + 1] * inv * acc1;
    out[(r + 2) * D_ + d] = rs_rows[rbase + 2] * inv * acc2;
    out[(r + 3) * D_ + d] = rs_rows[rbase + 3] * inv * acc3;
}

// ---------------------------------------------------------------------------
extern "C" void kernel_launch(void* const* d_in, const int* in_sizes, int n_in,
                              void* d_out, int out_size) {
    const float* h0     = (const float*)d_in[0];   // (B,N,H)
    const float* e      = (const float*)d_in[1];   // (B,N,N,FE)
    const float* w_fc   = (const float*)d_in[2];   // (D,H)
    const float* w_attn = (const float*)d_in[3];   // (2D+FE,)
    float* out = (float*)d_out;                    // (B,N,D)

    k_sisj<<<(B_ * N_) / 128, 128>>>(h0, w_fc, w_attn);
    k_row<<<B_ * N_, 256>>>(e, w_attn);
    k_zout<<<(B_ * N_) / RPB, 512>>>(h0, w_fc, out);
}